// round 1
// baseline (speedup 1.0000x reference)
#include <cuda_runtime.h>

#define B_ 16
#define N_ 2048
#define F_ 128
#define C1 32
#define TM 128
#define KT 32
#define NTILES (N_ / TM)   // 16

// Scratch (static device globals — no allocation allowed)
__device__ float g_T[B_ * N_ * C1];          // transform output (XW1, then H1W2)
__device__ float g_H[B_ * N_ * C1];          // layer-1 aggregated output
__device__ float g_poolpart[B_ * NTILES * C1];

__device__ __forceinline__ float elu_f(float x) {
    return x > 0.f ? x : (__expf(x) - 1.f);
}

// ---------------------------------------------------------------------------
// K1: T = X @ W1   (X [B*N,128] row-major, W1 [128,32])
// one row per thread, W1 in shared (broadcast reads)
// ---------------------------------------------------------------------------
__global__ void k_xw1(const float* __restrict__ X, const float* __restrict__ W1) {
    __shared__ float ws[F_ * C1];
    int tid = threadIdx.x;
    for (int i = tid; i < F_ * C1; i += 256) ws[i] = W1[i];
    __syncthreads();

    size_t row = (size_t)blockIdx.x * 256 + tid;
    const float4* xp = (const float4*)(X + row * F_);
    float acc[C1];
#pragma unroll
    for (int c = 0; c < C1; c++) acc[c] = 0.f;

    for (int k4 = 0; k4 < F_ / 4; k4++) {
        float4 xv = xp[k4];
        float xk[4] = {xv.x, xv.y, xv.z, xv.w};
#pragma unroll
        for (int i = 0; i < 4; i++) {
            int k = k4 * 4 + i;
#pragma unroll
            for (int c4 = 0; c4 < 8; c4++) {
                float4 w = *(const float4*)&ws[k * C1 + c4 * 4];
                acc[c4 * 4 + 0] += xk[i] * w.x;
                acc[c4 * 4 + 1] += xk[i] * w.y;
                acc[c4 * 4 + 2] += xk[i] * w.z;
                acc[c4 * 4 + 3] += xk[i] * w.w;
            }
        }
    }
    float4* op = (float4*)(g_T + row * C1);
#pragma unroll
    for (int j = 0; j < 8; j++)
        op[j] = make_float4(acc[j * 4], acc[j * 4 + 1], acc[j * 4 + 2], acc[j * 4 + 3]);
}

// ---------------------------------------------------------------------------
// K2/K4: aggregation  out = elu(A[b] @ g_T[b] + bias)
//   POOL=false: write to g_H
//   POOL=true : deterministic per-tile column sums into g_poolpart
// Tile: TM=128 rows x 32 cols, KT=32. 256 threads, 4x4 outputs per thread.
// ---------------------------------------------------------------------------
template <bool POOL>
__global__ void k_agg(const float* __restrict__ A, const float* __restrict__ bias) {
    __shared__ float As[TM][KT + 1];  // pad -> conflict-free column reads
    __shared__ float Ts[KT][C1];
    __shared__ float red[32][C1];

    int tid = threadIdx.x;                 // 256
    int b = blockIdx.y;
    int t0 = blockIdx.x * TM;
    const float* Ab = A + ((size_t)b * N_ + t0) * N_;
    const float* Tb = g_T + (size_t)b * N_ * C1;

    int tx = tid & 7;        // col group (cols tx*4 .. +3)
    int ty = tid >> 3;       // row group 0..31 (rows ty*4 .. +3)

    float acc[4][4];
#pragma unroll
    for (int r = 0; r < 4; r++)
#pragma unroll
        for (int c = 0; c < 4; c++) acc[r][c] = 0.f;

    for (int k0 = 0; k0 < N_; k0 += KT) {
        // load A tile: 128x32 = 1024 float4, 4 per thread (coalesced)
#pragma unroll
        for (int j = 0; j < 4; j++) {
            int f = tid + j * 256;         // 0..1023
            int r = f >> 3, c4 = (f & 7) * 4;
            float4 v = *(const float4*)(Ab + (size_t)r * N_ + k0 + c4);
            As[r][c4 + 0] = v.x;
            As[r][c4 + 1] = v.y;
            As[r][c4 + 2] = v.z;
            As[r][c4 + 3] = v.w;
        }
        // load T tile: 32x32 = 256 float4, 1 per thread (fully contiguous)
        {
            int r = tid >> 3, c4 = (tid & 7) * 4;
            *(float4*)&Ts[r][c4] = *(const float4*)(Tb + (size_t)(k0 + r) * C1 + c4);
        }
        __syncthreads();

#pragma unroll
        for (int kk = 0; kk < KT; kk++) {
            float4 tv = *(const float4*)&Ts[kk][tx * 4];
            float a0 = As[ty * 4 + 0][kk];
            float a1 = As[ty * 4 + 1][kk];
            float a2 = As[ty * 4 + 2][kk];
            float a3 = As[ty * 4 + 3][kk];
            acc[0][0] += a0 * tv.x; acc[0][1] += a0 * tv.y; acc[0][2] += a0 * tv.z; acc[0][3] += a0 * tv.w;
            acc[1][0] += a1 * tv.x; acc[1][1] += a1 * tv.y; acc[1][2] += a1 * tv.z; acc[1][3] += a1 * tv.w;
            acc[2][0] += a2 * tv.x; acc[2][1] += a2 * tv.y; acc[2][2] += a2 * tv.z; acc[2][3] += a2 * tv.w;
            acc[3][0] += a3 * tv.x; acc[3][1] += a3 * tv.y; acc[3][2] += a3 * tv.z; acc[3][3] += a3 * tv.w;
        }
        __syncthreads();
    }

    float4 bb = *(const float4*)&bias[tx * 4];
    float bc[4] = {bb.x, bb.y, bb.z, bb.w};

    if (!POOL) {
#pragma unroll
        for (int r = 0; r < 4; r++) {
            float4 o;
            o.x = elu_f(acc[r][0] + bc[0]);
            o.y = elu_f(acc[r][1] + bc[1]);
            o.z = elu_f(acc[r][2] + bc[2]);
            o.w = elu_f(acc[r][3] + bc[3]);
            *(float4*)&g_H[((size_t)b * N_ + t0 + ty * 4 + r) * C1 + tx * 4] = o;
        }
    } else {
        float cs[4] = {0.f, 0.f, 0.f, 0.f};
#pragma unroll
        for (int r = 0; r < 4; r++) {
#pragma unroll
            for (int c = 0; c < 4; c++) cs[c] += elu_f(acc[r][c] + bc[c]);
        }
        *(float4*)&red[ty][tx * 4] = make_float4(cs[0], cs[1], cs[2], cs[3]);
        __syncthreads();
        if (tid < C1) {
            float s = 0.f;
#pragma unroll
            for (int y = 0; y < 32; y++) s += red[y][tid];
            g_poolpart[((size_t)b * NTILES + blockIdx.x) * C1 + tid] = s;
        }
    }
}

// ---------------------------------------------------------------------------
// K3: g_T = g_H @ W2   (rows B*N, W2 [32,32])  — one row per thread
// ---------------------------------------------------------------------------
__global__ void k_hw2(const float* __restrict__ W2) {
    __shared__ float ws[C1 * C1];
    int tid = threadIdx.x;
    for (int i = tid; i < C1 * C1; i += 256) ws[i] = W2[i];
    __syncthreads();

    size_t row = (size_t)blockIdx.x * 256 + tid;
    float hv[C1];
    const float4* hp = (const float4*)(g_H + row * C1);
#pragma unroll
    for (int j = 0; j < 8; j++) {
        float4 v = hp[j];
        hv[j * 4 + 0] = v.x; hv[j * 4 + 1] = v.y; hv[j * 4 + 2] = v.z; hv[j * 4 + 3] = v.w;
    }
    float acc[C1];
#pragma unroll
    for (int c = 0; c < C1; c++) acc[c] = 0.f;
#pragma unroll
    for (int k = 0; k < C1; k++) {
        float hk = hv[k];
#pragma unroll
        for (int c4 = 0; c4 < 8; c4++) {
            float4 w = *(const float4*)&ws[k * C1 + c4 * 4];
            acc[c4 * 4 + 0] += hk * w.x;
            acc[c4 * 4 + 1] += hk * w.y;
            acc[c4 * 4 + 2] += hk * w.z;
            acc[c4 * 4 + 3] += hk * w.w;
        }
    }
    float4* op = (float4*)(g_T + row * C1);
#pragma unroll
    for (int j = 0; j < 8; j++)
        op[j] = make_float4(acc[j * 4], acc[j * 4 + 1], acc[j * 4 + 2], acc[j * 4 + 3]);
}

// ---------------------------------------------------------------------------
// K5: head. Reduce pool partials (fixed order), FC1+relu, FC2+sigmoid.
// Single block, 512 threads. Fully deterministic.
// ---------------------------------------------------------------------------
__global__ void k_head(const float* __restrict__ wf1, const float* __restrict__ bf1,
                       const float* __restrict__ wf2, const float* __restrict__ bf2,
                       float* __restrict__ out) {
    __shared__ float ps[B_ * C1];   // 512 pooled values
    __shared__ float srd[512];
    int tid = threadIdx.x;

    {   // pooled[b][c] = sum over tiles (fixed order)
        int b = tid >> 5, c = tid & 31;
        float s = 0.f;
#pragma unroll
        for (int t = 0; t < NTILES; t++)
            s += g_poolpart[((size_t)b * NTILES + t) * C1 + c];
        ps[tid] = s;
    }
    __syncthreads();

    for (int b = 0; b < B_; b++) {
        float z = bf1[tid];
#pragma unroll
        for (int k = 0; k < C1; k++)
            z += ps[b * C1 + k] * wf1[k * 512 + tid];
        float h = fmaxf(z, 0.f);
        srd[tid] = h * wf2[tid];
        __syncthreads();
        for (int s = 256; s > 0; s >>= 1) {
            if (tid < s) srd[tid] += srd[tid + s];
            __syncthreads();
        }
        if (tid == 0) out[b] = 1.f / (1.f + __expf(-(srd[0] + bf2[0])));
        __syncthreads();
    }
}

// ---------------------------------------------------------------------------
extern "C" void kernel_launch(void* const* d_in, const int* in_sizes, int n_in,
                              void* d_out, int out_size) {
    const float* x   = (const float*)d_in[0];
    const float* a   = (const float*)d_in[1];
    const float* w1  = (const float*)d_in[2];
    const float* b1  = (const float*)d_in[3];
    const float* w2  = (const float*)d_in[4];
    const float* b2  = (const float*)d_in[5];
    const float* wf1 = (const float*)d_in[6];
    const float* bf1 = (const float*)d_in[7];
    const float* wf2 = (const float*)d_in[8];
    const float* bf2 = (const float*)d_in[9];
    float* out = (float*)d_out;

    (void)in_sizes; (void)n_in; (void)out_size;

    dim3 gagg(NTILES, B_);

    k_xw1<<<(B_ * N_) / 256, 256>>>(x, w1);          // T  = X @ W1
    k_agg<false><<<gagg, 256>>>(a, b1);              // H  = elu(A @ T + b1)
    k_hw2<<<(B_ * N_) / 256, 256>>>(w2);             // T  = H @ W2
    k_agg<true><<<gagg, 256>>>(a, b2);               // poolpart = colsum(elu(A @ T + b2))
    k_head<<<1, 512>>>(wf1, bf1, wf2, bf2, out);     // FC head -> out[16]
}

// round 2
// speedup vs baseline: 2.2774x; 2.2774x over previous
#include <cuda_runtime.h>
#include <cstdint>

#define B_ 16
#define N_ 2048
#define F_ 128
#define C1 32
#define TM 128
#define KT 32
#define PA 36   // As smem pitch (floats): bank = 4*g+q -> conflict-free A frags
#define PT 40   // Ts smem pitch (floats): bank = 8*q+g -> conflict-free B frags
#define NTILES (N_ / TM)   // 16

// Scratch (static device globals — no allocation allowed)
__device__ float g_T[B_ * N_ * C1];          // transform output (XW1, then H1W2)
__device__ float g_H[B_ * N_ * C1];          // layer-1 aggregated output
__device__ float g_poolpart[B_ * NTILES * C1];

__device__ __forceinline__ float elu_f(float x) {
    return x > 0.f ? x : (__expf(x) - 1.f);
}

__device__ __forceinline__ uint32_t f2tf(float f) {
    uint32_t r;
    asm("cvt.rna.tf32.f32 %0, %1;" : "=r"(r) : "f"(f));
    return r;
}

__device__ __forceinline__ void cp16(void* dst, const void* src) {
    uint32_t d = (uint32_t)__cvta_generic_to_shared(dst);
    asm volatile("cp.async.cg.shared.global [%0], [%1], 16;\n" :: "r"(d), "l"(src));
}

__device__ __forceinline__ void mma_tf32(float c[4], uint32_t a0, uint32_t a1,
                                         uint32_t a2, uint32_t a3,
                                         uint32_t b0, uint32_t b1) {
    asm volatile(
        "mma.sync.aligned.m16n8k8.row.col.f32.tf32.tf32.f32 "
        "{%0,%1,%2,%3}, {%4,%5,%6,%7}, {%8,%9}, {%0,%1,%2,%3};"
        : "+f"(c[0]), "+f"(c[1]), "+f"(c[2]), "+f"(c[3])
        : "r"(a0), "r"(a1), "r"(a2), "r"(a3), "r"(b0), "r"(b1));
}

// ---------------------------------------------------------------------------
// K1: T = X @ W1   (X [B*N,128] row-major, W1 [128,32])
// ---------------------------------------------------------------------------
__global__ void k_xw1(const float* __restrict__ X, const float* __restrict__ W1) {
    __shared__ float ws[F_ * C1];
    int tid = threadIdx.x;
    for (int i = tid; i < F_ * C1; i += 256) ws[i] = W1[i];
    __syncthreads();

    size_t row = (size_t)blockIdx.x * 256 + tid;
    const float4* xp = (const float4*)(X + row * F_);
    float acc[C1];
#pragma unroll
    for (int c = 0; c < C1; c++) acc[c] = 0.f;

    for (int k4 = 0; k4 < F_ / 4; k4++) {
        float4 xv = xp[k4];
        float xk[4] = {xv.x, xv.y, xv.z, xv.w};
#pragma unroll
        for (int i = 0; i < 4; i++) {
            int k = k4 * 4 + i;
#pragma unroll
            for (int c4 = 0; c4 < 8; c4++) {
                float4 w = *(const float4*)&ws[k * C1 + c4 * 4];
                acc[c4 * 4 + 0] += xk[i] * w.x;
                acc[c4 * 4 + 1] += xk[i] * w.y;
                acc[c4 * 4 + 2] += xk[i] * w.z;
                acc[c4 * 4 + 3] += xk[i] * w.w;
            }
        }
    }
    float4* op = (float4*)(g_T + row * C1);
#pragma unroll
    for (int j = 0; j < 8; j++)
        op[j] = make_float4(acc[j * 4], acc[j * 4 + 1], acc[j * 4 + 2], acc[j * 4 + 3]);
}

// ---------------------------------------------------------------------------
// K2/K4: aggregation  out = elu(A[b] @ g_T[b] + bias)  via TF32 tensor cores
//   128x32 tile per block, 8 warps x (16x32), mma.m16n8k8, cp.async 2-stage.
// ---------------------------------------------------------------------------
template <bool POOL>
__global__ void __launch_bounds__(256, 4)
k_agg(const float* __restrict__ A, const float* __restrict__ bias) {
    __shared__ __align__(16) float As[2][TM][PA];
    __shared__ __align__(16) float Ts[2][KT][PT];
    __shared__ float red[8][C1];

    const int tid = threadIdx.x;            // 256
    const int b = blockIdx.y;
    const int t0 = blockIdx.x * TM;
    const float* Ab = A + ((size_t)b * N_ + t0) * N_;
    const float* Tb = g_T + (size_t)b * N_ * C1;

    const int wid = tid >> 5;               // 0..7 -> rows wid*16..+15
    const int lane = tid & 31;
    const int g = lane >> 2;                // 0..7
    const int q = lane & 3;                 // 0..3
    const int rw = wid * 16;

    // cp.async load indices
    const int lar = tid >> 3;               // A rows 0..31 (x4 batches of 32)
    const int lac = (tid & 7) * 4;          // A col group

    float acc[4][4];
#pragma unroll
    for (int j = 0; j < 4; j++)
#pragma unroll
        for (int i = 0; i < 4; i++) acc[j][i] = 0.f;

    // prologue: stage 0
    {
#pragma unroll
        for (int j = 0; j < 4; j++)
            cp16(&As[0][lar + j * 32][lac], Ab + (size_t)(lar + j * 32) * N_ + lac);
        cp16(&Ts[0][lar][lac], Tb + (size_t)lar * C1 + lac);
        asm volatile("cp.async.commit_group;\n");
    }

    const int NKT = N_ / KT;                // 64
    for (int kt = 0; kt < NKT; kt++) {
        const int cur = kt & 1;
        if (kt + 1 < NKT) {
            const int nxt = cur ^ 1;
            const int k0 = (kt + 1) * KT;
#pragma unroll
            for (int j = 0; j < 4; j++)
                cp16(&As[nxt][lar + j * 32][lac], Ab + (size_t)(lar + j * 32) * N_ + k0 + lac);
            cp16(&Ts[nxt][lar][lac], Tb + (size_t)(k0 + lar) * C1 + lac);
            asm volatile("cp.async.commit_group;\n");
            asm volatile("cp.async.wait_group 1;\n");
        } else {
            asm volatile("cp.async.wait_group 0;\n");
        }
        __syncthreads();

#pragma unroll
        for (int k8 = 0; k8 < KT / 8; k8++) {
            const int kk = k8 * 8;
            uint32_t A0 = f2tf(As[cur][rw + g][kk + q]);
            uint32_t A1 = f2tf(As[cur][rw + g + 8][kk + q]);
            uint32_t A2 = f2tf(As[cur][rw + g][kk + q + 4]);
            uint32_t A3 = f2tf(As[cur][rw + g + 8][kk + q + 4]);
#pragma unroll
            for (int j = 0; j < 4; j++) {
                uint32_t B0 = f2tf(Ts[cur][kk + q][8 * j + g]);
                uint32_t B1 = f2tf(Ts[cur][kk + q + 4][8 * j + g]);
                mma_tf32(acc[j], A0, A1, A2, A3, B0, B1);
            }
        }
        __syncthreads();
    }

    if (!POOL) {
#pragma unroll
        for (int j = 0; j < 4; j++) {
            const int col = 8 * j + 2 * q;
            const float bc0 = bias[col], bc1 = bias[col + 1];
            const size_t r0 = ((size_t)b * N_ + t0 + rw + g) * C1 + col;
            const size_t r1 = r0 + 8 * C1;
            float2 v0 = make_float2(elu_f(acc[j][0] + bc0), elu_f(acc[j][1] + bc1));
            float2 v1 = make_float2(elu_f(acc[j][2] + bc0), elu_f(acc[j][3] + bc1));
            *(float2*)&g_H[r0] = v0;
            *(float2*)&g_H[r1] = v1;
        }
    } else {
#pragma unroll
        for (int j = 0; j < 4; j++) {
            const int col = 8 * j + 2 * q;
            const float bc0 = bias[col], bc1 = bias[col + 1];
            float s0 = elu_f(acc[j][0] + bc0) + elu_f(acc[j][2] + bc0);
            float s1 = elu_f(acc[j][1] + bc1) + elu_f(acc[j][3] + bc1);
#pragma unroll
            for (int m = 4; m < 32; m <<= 1) {
                s0 += __shfl_xor_sync(0xffffffffu, s0, m);
                s1 += __shfl_xor_sync(0xffffffffu, s1, m);
            }
            if (g == 0) {
                red[wid][col] = s0;
                red[wid][col + 1] = s1;
            }
        }
        __syncthreads();
        if (tid < C1) {
            float s = 0.f;
#pragma unroll
            for (int y = 0; y < 8; y++) s += red[y][tid];
            g_poolpart[((size_t)b * NTILES + blockIdx.x) * C1 + tid] = s;
        }
    }
}

// ---------------------------------------------------------------------------
// K3: g_T = g_H @ W2   (rows B*N, W2 [32,32])
// ---------------------------------------------------------------------------
__global__ void k_hw2(const float* __restrict__ W2) {
    __shared__ float ws[C1 * C1];
    int tid = threadIdx.x;
    for (int i = tid; i < C1 * C1; i += 256) ws[i] = W2[i];
    __syncthreads();

    size_t row = (size_t)blockIdx.x * 256 + tid;
    float hv[C1];
    const float4* hp = (const float4*)(g_H + row * C1);
#pragma unroll
    for (int j = 0; j < 8; j++) {
        float4 v = hp[j];
        hv[j * 4 + 0] = v.x; hv[j * 4 + 1] = v.y; hv[j * 4 + 2] = v.z; hv[j * 4 + 3] = v.w;
    }
    float acc[C1];
#pragma unroll
    for (int c = 0; c < C1; c++) acc[c] = 0.f;
#pragma unroll
    for (int k = 0; k < C1; k++) {
        float hk = hv[k];
#pragma unroll
        for (int c4 = 0; c4 < 8; c4++) {
            float4 w = *(const float4*)&ws[k * C1 + c4 * 4];
            acc[c4 * 4 + 0] += hk * w.x;
            acc[c4 * 4 + 1] += hk * w.y;
            acc[c4 * 4 + 2] += hk * w.z;
            acc[c4 * 4 + 3] += hk * w.w;
        }
    }
    float4* op = (float4*)(g_T + row * C1);
#pragma unroll
    for (int j = 0; j < 8; j++)
        op[j] = make_float4(acc[j * 4], acc[j * 4 + 1], acc[j * 4 + 2], acc[j * 4 + 3]);
}

// ---------------------------------------------------------------------------
// K5: head, one block per batch. Deterministic fixed-order reductions.
// ---------------------------------------------------------------------------
__global__ void k_head(const float* __restrict__ wf1, const float* __restrict__ bf1,
                       const float* __restrict__ wf2, const float* __restrict__ bf2,
                       float* __restrict__ out) {
    __shared__ float ps[C1];
    __shared__ float srd[512];
    const int b = blockIdx.x;
    const int tid = threadIdx.x;   // 512

    if (tid < C1) {
        float s = 0.f;
#pragma unroll
        for (int t = 0; t < NTILES; t++)
            s += g_poolpart[((size_t)b * NTILES + t) * C1 + tid];
        ps[tid] = s;
    }
    __syncthreads();

    float z = bf1[tid];
#pragma unroll
    for (int k = 0; k < C1; k++)
        z += ps[k] * wf1[k * 512 + tid];
    srd[tid] = fmaxf(z, 0.f) * wf2[tid];
    __syncthreads();
    for (int s = 256; s > 0; s >>= 1) {
        if (tid < s) srd[tid] += srd[tid + s];
        __syncthreads();
    }
    if (tid == 0) out[b] = 1.f / (1.f + __expf(-(srd[0] + bf2[0])));
}

// ---------------------------------------------------------------------------
extern "C" void kernel_launch(void* const* d_in, const int* in_sizes, int n_in,
                              void* d_out, int out_size) {
    const float* x   = (const float*)d_in[0];
    const float* a   = (const float*)d_in[1];
    const float* w1  = (const float*)d_in[2];
    const float* b1  = (const float*)d_in[3];
    const float* w2  = (const float*)d_in[4];
    const float* b2  = (const float*)d_in[5];
    const float* wf1 = (const float*)d_in[6];
    const float* bf1 = (const float*)d_in[7];
    const float* wf2 = (const float*)d_in[8];
    const float* bf2 = (const float*)d_in[9];
    float* out = (float*)d_out;

    (void)in_sizes; (void)n_in; (void)out_size;

    dim3 gagg(NTILES, B_);

    k_xw1<<<(B_ * N_) / 256, 256>>>(x, w1);          // T  = X @ W1
    k_agg<false><<<gagg, 256>>>(a, b1);              // H  = elu(A @ T + b1)
    k_hw2<<<(B_ * N_) / 256, 256>>>(w2);             // T  = H @ W2
    k_agg<true><<<gagg, 256>>>(a, b2);               // poolpart = colsum(elu(A @ T + b2))
    k_head<<<B_, 512>>>(wf1, bf1, wf2, bf2, out);    // FC head -> out[16]
}

// round 5
// speedup vs baseline: 2.5323x; 1.1119x over previous
#include <cuda_runtime.h>
#include <cstdint>

#define B_ 16
#define N_ 2048
#define F_ 128
#define C1 32
#define TM 128
#define KT 32
#define PA 36   // As smem pitch (floats): conflict-free A frags
#define PT 40   // Ts smem pitch (uints): conflict-free B frags
#define NTILES (N_ / TM)   // 16

// Scratch (static device globals — no allocation allowed)
__device__ uint32_t g_Tt[B_ * N_ * C1];      // transform output as tf32 bits
__device__ float    g_H[B_ * N_ * C1];       // layer-1 aggregated output (fp32)
__device__ uint32_t g_W1t[F_ * C1];          // W1 as tf32 bits
__device__ uint32_t g_W2t[C1 * C1];          // W2 as tf32 bits
__device__ float    g_poolpart[B_ * NTILES * C1];

__device__ __forceinline__ float elu_f(float x) {
    return x > 0.f ? x : (__expf(x) - 1.f);
}

__device__ __forceinline__ uint32_t f2tf(float f) {
    uint32_t r;
    asm("cvt.rna.tf32.f32 %0, %1;" : "=r"(r) : "f"(f));
    return r;
}

__device__ __forceinline__ void cp16(void* dst, const void* src) {
    uint32_t d = (uint32_t)__cvta_generic_to_shared(dst);
    asm volatile("cp.async.cg.shared.global [%0], [%1], 16;\n" :: "r"(d), "l"(src));
}

__device__ __forceinline__ void mma_tf32(float c[4], uint32_t a0, uint32_t a1,
                                         uint32_t a2, uint32_t a3,
                                         uint32_t b0, uint32_t b1) {
    asm volatile(
        "mma.sync.aligned.m16n8k8.row.col.f32.tf32.tf32.f32 "
        "{%0,%1,%2,%3}, {%4,%5,%6,%7}, {%8,%9}, {%0,%1,%2,%3};"
        : "+f"(c[0]), "+f"(c[1]), "+f"(c[2]), "+f"(c[3])
        : "r"(a0), "r"(a1), "r"(a2), "r"(a3), "r"(b0), "r"(b1));
}

// ---------------------------------------------------------------------------
// K0: convert W1, W2 to tf32 bits (tiny)
// ---------------------------------------------------------------------------
__global__ void k_prep(const float* __restrict__ W1, const float* __restrict__ W2) {
    int tid = threadIdx.x;
    for (int i = tid; i < F_ * C1; i += 256) g_W1t[i] = f2tf(W1[i]);
    if (tid < C1 * C1 - 768) {}
    for (int i = tid; i < C1 * C1; i += 256) g_W2t[i] = f2tf(W2[i]);
}

// ---------------------------------------------------------------------------
// Unified TF32 tensor-core GEMM: OUT = epilogue(A @ B + bias)
//   MODE 0: XW1  A=x   [32768,128] lda=128,  K=128,  out: g_Tt (tf32)
//   MODE 1: AGG1 A=a[b][2048,2048] lda=2048, K=2048, out: g_H = elu(.+b1)
//   MODE 2: HW2  A=g_H [32768,32]  lda=32,   K=32,   out: g_Tt (tf32)
//   MODE 3: AGG2 A=a[b]                       K=2048, out: poolpart (elu+colsum)
// Tile: 128 rows x 32 cols per block, 8 warps x (16x32), cp.async 2-stage.
// ---------------------------------------------------------------------------
template <int MODE>
__global__ void __launch_bounds__(256, 4)
k_gemm(const float* __restrict__ Abase, const float* __restrict__ bias) {
    constexpr bool AGG = (MODE == 1 || MODE == 3);
    constexpr int LDA = (MODE == 0) ? F_ : (AGG ? N_ : C1);
    constexpr int KTOT = LDA;            // happens to coincide for all modes
    constexpr int NKT = KTOT / KT;

    __shared__ __align__(16) float As[2][TM][PA];
    __shared__ __align__(16) uint32_t Ts[2][KT][PT];
    __shared__ float red[8][C1];

    const int tid = threadIdx.x;            // 256
    const int b = AGG ? blockIdx.y : 0;
    const int t0 = blockIdx.x * TM;

    const float* A = AGG ? (MODE == 2 ? nullptr : Abase) + (size_t)b * N_ * N_ + (size_t)t0 * N_
                         : (MODE == 2 ? (const float*)g_H : Abase) + (size_t)t0 * LDA;
    const uint32_t* Bp = AGG ? g_Tt + (size_t)b * N_ * C1
                             : (MODE == 0 ? g_W1t : g_W2t);

    const int wid = tid >> 5;               // 0..7 -> rows wid*16..+15
    const int lane = tid & 31;
    const int g = lane >> 2;                // 0..7
    const int q = lane & 3;                 // 0..3
    const int rw = wid * 16;

    const int lar = tid >> 3;               // 0..31
    const int lac = (tid & 7) * 4;

    // per-thread source pointers (advance by KT each tile)
    const float* asrc0 = A + (size_t)lar * LDA + lac;
    const uint32_t* bsrc = Bp + lar * C1 + lac;

    float acc[4][4];
#pragma unroll
    for (int j = 0; j < 4; j++)
#pragma unroll
        for (int i = 0; i < 4; i++) acc[j][i] = 0.f;

    // prologue: stage 0
#pragma unroll
    for (int j = 0; j < 4; j++)
        cp16(&As[0][lar + j * 32][lac], asrc0 + (size_t)j * 32 * LDA);
    cp16(&Ts[0][lar][lac], bsrc);
    asm volatile("cp.async.commit_group;\n");

    for (int kt = 0; kt < NKT; kt++) {
        const int cur = kt & 1;
        if (kt + 1 < NKT) {
            const int nxt = cur ^ 1;
            const float* an = asrc0 + (kt + 1) * KT;
            const uint32_t* bn = bsrc + (kt + 1) * KT * C1;
#pragma unroll
            for (int j = 0; j < 4; j++)
                cp16(&As[nxt][lar + j * 32][lac], an + (size_t)j * 32 * LDA);
            cp16(&Ts[nxt][lar][lac], bn);
            asm volatile("cp.async.commit_group;\n");
            asm volatile("cp.async.wait_group 1;\n");
        } else {
            asm volatile("cp.async.wait_group 0;\n");
        }
        __syncthreads();

#pragma unroll
        for (int k8 = 0; k8 < KT / 8; k8++) {
            const int kk = k8 * 8;
            uint32_t A0 = f2tf(As[cur][rw + g][kk + q]);
            uint32_t A1 = f2tf(As[cur][rw + g + 8][kk + q]);
            uint32_t A2 = f2tf(As[cur][rw + g][kk + q + 4]);
            uint32_t A3 = f2tf(As[cur][rw + g + 8][kk + q + 4]);
#pragma unroll
            for (int j = 0; j < 4; j++) {
                uint32_t B0 = Ts[cur][kk + q][8 * j + g];
                uint32_t B1 = Ts[cur][kk + q + 4][8 * j + g];
                mma_tf32(acc[j], A0, A1, A2, A3, B0, B1);
            }
        }
        __syncthreads();
    }

    if (MODE == 0 || MODE == 2) {
        // store tf32 bits to g_Tt
#pragma unroll
        for (int j = 0; j < 4; j++) {
            const int col = 8 * j + 2 * q;
            const size_t r0 = ((size_t)t0 + rw + g) * C1 + col;
            const size_t r1 = r0 + 8 * C1;
            uint2 v0 = make_uint2(f2tf(acc[j][0]), f2tf(acc[j][1]));
            uint2 v1 = make_uint2(f2tf(acc[j][2]), f2tf(acc[j][3]));
            *(uint2*)&g_Tt[r0] = v0;
            *(uint2*)&g_Tt[r1] = v1;
        }
    } else if (MODE == 1) {
#pragma unroll
        for (int j = 0; j < 4; j++) {
            const int col = 8 * j + 2 * q;
            const float bc0 = bias[col], bc1 = bias[col + 1];
            const size_t r0 = ((size_t)b * N_ + t0 + rw + g) * C1 + col;
            const size_t r1 = r0 + 8 * C1;
            float2 v0 = make_float2(elu_f(acc[j][0] + bc0), elu_f(acc[j][1] + bc1));
            float2 v1 = make_float2(elu_f(acc[j][2] + bc0), elu_f(acc[j][3] + bc1));
            *(float2*)&g_H[r0] = v0;
            *(float2*)&g_H[r1] = v1;
        }
    } else {
#pragma unroll
        for (int j = 0; j < 4; j++) {
            const int col = 8 * j + 2 * q;
            const float bc0 = bias[col], bc1 = bias[col + 1];
            float s0 = elu_f(acc[j][0] + bc0) + elu_f(acc[j][2] + bc0);
            float s1 = elu_f(acc[j][1] + bc1) + elu_f(acc[j][3] + bc1);
#pragma unroll
            for (int m = 4; m < 32; m <<= 1) {
                s0 += __shfl_xor_sync(0xffffffffu, s0, m);
                s1 += __shfl_xor_sync(0xffffffffu, s1, m);
            }
            if (g == 0) {
                red[wid][col] = s0;
                red[wid][col + 1] = s1;
            }
        }
        __syncthreads();
        if (tid < C1) {
            float s = 0.f;
#pragma unroll
            for (int y = 0; y < 8; y++) s += red[y][tid];
            g_poolpart[((size_t)b * NTILES + blockIdx.x) * C1 + tid] = s;
        }
    }
}

// ---------------------------------------------------------------------------
// K5: head, one block per batch. Deterministic fixed-order reductions.
// ---------------------------------------------------------------------------
__global__ void k_head(const float* __restrict__ wf1, const float* __restrict__ bf1,
                       const float* __restrict__ wf2, const float* __restrict__ bf2,
                       float* __restrict__ out) {
    __shared__ float ps[C1];
    __shared__ float srd[512];
    const int b = blockIdx.x;
    const int tid = threadIdx.x;   // 512

    if (tid < C1) {
        float s = 0.f;
#pragma unroll
        for (int t = 0; t < NTILES; t++)
            s += g_poolpart[((size_t)b * NTILES + t) * C1 + tid];
        ps[tid] = s;
    }
    __syncthreads();

    float z = bf1[tid];
#pragma unroll
    for (int k = 0; k < C1; k++)
        z += ps[k] * wf1[k * 512 + tid];
    srd[tid] = fmaxf(z, 0.f) * wf2[tid];
    __syncthreads();
    for (int s = 256; s > 0; s >>= 1) {
        if (tid < s) srd[tid] += srd[tid + s];
        __syncthreads();
    }
    if (tid == 0) out[b] = 1.f / (1.f + __expf(-(srd[0] + bf2[0])));
}

// ---------------------------------------------------------------------------
extern "C" void kernel_launch(void* const* d_in, const int* in_sizes, int n_in,
                              void* d_out, int out_size) {
    const float* x   = (const float*)d_in[0];
    const float* a   = (const float*)d_in[1];
    const float* w1  = (const float*)d_in[2];
    const float* b1  = (const float*)d_in[3];
    const float* w2  = (const float*)d_in[4];
    const float* b2  = (const float*)d_in[5];
    const float* wf1 = (const float*)d_in[6];
    const float* bf1 = (const float*)d_in[7];
    const float* wf2 = (const float*)d_in[8];
    const float* bf2 = (const float*)d_in[9];
    float* out = (float*)d_out;

    (void)in_sizes; (void)n_in; (void)out_size;

    // Ask for max shared-memory carveout so 4 CTAs (4x48KB) fit per SM.
    cudaFuncSetAttribute(k_gemm<0>, cudaFuncAttributePreferredSharedMemoryCarveout, 100);
    cudaFuncSetAttribute(k_gemm<1>, cudaFuncAttributePreferredSharedMemoryCarveout, 100);
    cudaFuncSetAttribute(k_gemm<2>, cudaFuncAttributePreferredSharedMemoryCarveout, 100);
    cudaFuncSetAttribute(k_gemm<3>, cudaFuncAttributePreferredSharedMemoryCarveout, 100);

    dim3 gagg(NTILES, B_);

    k_prep<<<1, 256>>>(w1, w2);                        // W -> tf32
    k_gemm<0><<<(B_ * N_) / TM, 256>>>(x, nullptr);    // g_Tt = X @ W1
    k_gemm<1><<<gagg, 256>>>(a, b1);                   // g_H  = elu(A @ T + b1)
    k_gemm<2><<<(B_ * N_) / TM, 256>>>(nullptr, nullptr); // g_Tt = H @ W2
    k_gemm<3><<<gagg, 256>>>(a, b2);                   // poolpart
    k_head<<<B_, 512>>>(wf1, bf1, wf2, bf2, out);      // FC head -> out[16]
}